// round 14
// baseline (speedup 1.0000x reference)
#include <cuda_runtime.h>
#include <cuda_fp16.h>
#include <math.h>

// ---------------- problem constants ----------------
#define BB 4
#define LL 512
#define VV 32000
#define DD 1024
#define HH 16
#define HD 64
#define NLAYER 2
#define EE 8
#define KK 2
#define FF 4096
#define SS (BB*LL)      // 2048
#define CAP 320
#define D3 (3*DD)       // 3072

typedef __half h16;

// ---------------- static scratch (f32) ----------------
__device__ float g_x[SS*DD];
__device__ float g_qkv[SS*D3];
__device__ float g_sc[BB*HH*LL*LL];     // 64 MB scores
__device__ float g_av[SS*DD];
__device__ float g_tmp[SS*DD];
__device__ float g_oe[EE*CAP*DD];
__device__ int   g_topi[SS*2];
__device__ float g_topw[SS*2];
__device__ int   g_slot[EE*CAP];
__device__ float g_slotw[EE*CAP];

// ---------------- fp16 activation buffers ----------------
__device__ h16 g_xh[SS*DD];
__device__ h16 g_qh[SS*DD];
__device__ h16 g_kh[SS*DD];
__device__ h16 g_vth[SS*DD];            // V^T per head [bh, d, l]
__device__ h16 g_ph[BB*HH*LL*LL];       // probs fp16 (32MB)
__device__ h16 g_attnh[SS*DD];
__device__ h16 g_xeh[EE*CAP*DD];
__device__ h16 g_hh[EE*CAP*FF];

// ---------------- fp16 weights (converted once/launch) ----------------
__device__ h16 g_wih[NLAYER*D3*DD];
__device__ h16 g_woh[NLAYER*DD*DD];
__device__ h16 g_w1h[NLAYER*EE*FF*DD];
__device__ h16 g_w2h[NLAYER*EE*DD*FF];
__device__ h16 g_dwh[VV*DD];

// ---------------- reductions ----------------
__device__ __forceinline__ float blockReduceSum(float v){
    __shared__ float sh[32];
    int lane = threadIdx.x & 31, wid = threadIdx.x >> 5;
    int nw = (blockDim.x + 31) >> 5;
    #pragma unroll
    for (int o = 16; o > 0; o >>= 1) v += __shfl_down_sync(0xffffffffu, v, o);
    __syncthreads();
    if (lane == 0) sh[wid] = v;
    __syncthreads();
    if (wid == 0) {
        v = (lane < nw) ? sh[lane] : 0.f;
        #pragma unroll
        for (int o = 16; o > 0; o >>= 1) v += __shfl_down_sync(0xffffffffu, v, o);
        if (lane == 0) sh[0] = v;
    }
    __syncthreads();
    return sh[0];
}

__device__ __forceinline__ float blockReduceMax(float v){
    __shared__ float sh[32];
    int lane = threadIdx.x & 31, wid = threadIdx.x >> 5;
    int nw = (blockDim.x + 31) >> 5;
    #pragma unroll
    for (int o = 16; o > 0; o >>= 1) v = fmaxf(v, __shfl_down_sync(0xffffffffu, v, o));
    __syncthreads();
    if (lane == 0) sh[wid] = v;
    __syncthreads();
    if (wid == 0) {
        v = (lane < nw) ? sh[lane] : -1e30f;
        #pragma unroll
        for (int o = 16; o > 0; o >>= 1) v = fmaxf(v, __shfl_down_sync(0xffffffffu, v, o));
        if (lane == 0) sh[0] = v;
    }
    __syncthreads();
    return sh[0];
}

// ---------------- helpers ----------------
#define MMA_F16(d, a, b) \
    asm volatile("mma.sync.aligned.m16n8k16.row.col.f32.f16.f16.f32 " \
        "{%0,%1,%2,%3},{%4,%5,%6,%7},{%8,%9},{%0,%1,%2,%3};" \
        : "+f"(d[0]), "+f"(d[1]), "+f"(d[2]), "+f"(d[3]) \
        : "r"(a[0]), "r"(a[1]), "r"(a[2]), "r"(a[3]), "r"(b[0]), "r"(b[1]))

#define LDSM4(r0, r1, r2, r3, addr) \
    asm volatile("ldmatrix.sync.aligned.m8n8.x4.shared.b16 {%0,%1,%2,%3}, [%4];" \
        : "=r"(r0), "=r"(r1), "=r"(r2), "=r"(r3) : "r"(addr))

__device__ __forceinline__ unsigned h2pack(float x, float y){
    __half2 H; H.x = __float2half_rn(x); H.y = __float2half_rn(y);
    return *(unsigned*)&H;
}
__device__ __forceinline__ void cp16(unsigned dst, const void* src, bool pred){
    asm volatile("cp.async.cg.shared.global [%0], [%1], 16, %2;"
        :: "r"(dst), "l"(src), "r"(pred ? 16 : 0));
}

// ============================================================
// Pure-fp16 tensor-core GEMM (single pass), K-chunk 64:
//   C = act(alpha * A(MxK) * B(NxK)^T + bias)
// Block 128x128x64, 8 warps, warp tile 64x32, m16n8k16.
// 2-stage cp.async, 2 barriers/iter.
// Mainloop/warp/iter: 8 cp.async + 24 LDSM + 128 MMA.
// ============================================================
#define GBM 128
#define GBN 128
#define GBK 64
#define LDW 36                            // row stride in 32-bit words (32 data + 4 pad)
#define ROW_B (LDW * 4)                   // 144 B
#define TILE_B (GBM * ROW_B)              // 18432 B per tile
#define STAGE_B (2u * TILE_B)             // A + B = 36864 B
#define NSTAGE 2
#define GEMM_SMEM_BYTES (NSTAGE * STAGE_B)  // 73728 B

__global__ void __launch_bounds__(256, 2)
gemm_h16(const h16* __restrict__ A, const h16* __restrict__ Bm,
         const float* __restrict__ bias, float* __restrict__ C,
         h16* __restrict__ Chalf,
         int M, int N, int K, int lda, int ldb, int ldc,
         long aStride, long bStride, long cStride, long biasStride,
         float alpha, int relu, int causal, int kcap)
{
    extern __shared__ char smem[];
    int m0 = blockIdx.x * GBM;
    int n0 = blockIdx.y * GBN;
    if (causal && n0 > m0 + GBM - 1) return;             // fully-masked causal block
    if (kcap) { int ke = m0 + GBM; if (ke < K) K = ke; } // zero prob cols past diag

    int z = blockIdx.z;
    A  += (long)z * aStride;
    Bm += (long)z * bStride;
    if (C)     C     += (long)z * cStride;
    if (Chalf) Chalf += (long)z * cStride;
    if (bias)  bias  += (long)z * biasStride;

    int tid = threadIdx.x;
    int wid = tid >> 5, lane = tid & 31;
    int wm = (wid & 1) * 64;
    int wn = (wid >> 1) * 32;

    float c[4][4][4];
    #pragma unroll
    for (int i = 0; i < 4; i++)
        #pragma unroll
        for (int j = 0; j < 4; j++)
            #pragma unroll
            for (int r = 0; r < 4; r++) c[i][j][r] = 0.f;

    // cp.async mapping: thread t -> row t>>1, 64B segment (t&1), 4 chunks of 16B
    int cpRow = tid >> 1;
    int cpSeg = tid & 1;
    int gmA = m0 + cpRow;  bool okA = gmA < M;  if (!okA) gmA = 0;
    int gnB = n0 + cpRow;  bool okB = gnB < N;  if (!okB) gnB = 0;

    unsigned sbase = (unsigned)__cvta_generic_to_shared(smem);
    unsigned rowOff = (unsigned)(cpRow * ROW_B + cpSeg * 64);

    auto issueCp = [&](int kt, int s) {
        unsigned base = sbase + s * STAGE_B;
        const h16* pa = A  + (long)gmA * lda + kt + cpSeg * 32;
        const h16* pb = Bm + (long)gnB * ldb + kt + cpSeg * 32;
        #pragma unroll
        for (int cch = 0; cch < 4; cch++) {
            cp16(base + rowOff + cch * 16,          pa + cch * 8, okA);
            cp16(base + TILE_B + rowOff + cch * 16, pb + cch * 8, okB);
        }
        asm volatile("cp.async.commit_group;" ::: "memory");
    };

    // ldmatrix per-thread offsets (words)
    int aoff = (lane & 15) * LDW + ((lane >> 4) << 2);
    int boff = ((lane & 7) + ((lane >> 4) & 1) * 8) * LDW + ((lane >> 3) & 1) * 4;

    int nIter = K / GBK;
    issueCp(0, 0);
    if (nIter > 1) issueCp(GBK, 1);

    for (int it = 0; it < nIter; it++) {
        if (it < nIter - 1) asm volatile("cp.async.wait_group 1;" ::: "memory");
        else                asm volatile("cp.async.wait_group 0;" ::: "memory");
        __syncthreads();   // stage it&1 visible to all

        unsigned sA = sbase + (it & 1) * STAGE_B;
        unsigned sB = sA + TILE_B;

        #pragma unroll
        for (int ks = 0; ks < 4; ks++) {
            int kw = ks * 8;
            unsigned ah[4][4], bh[4][2];
            #pragma unroll
            for (int i = 0; i < 4; i++) {
                unsigned off = ((wm + i * 16) * LDW + aoff + kw) * 4;
                LDSM4(ah[i][0], ah[i][1], ah[i][2], ah[i][3], sA + off);
            }
            #pragma unroll
            for (int p = 0; p < 2; p++) {
                unsigned off = ((wn + p * 16) * LDW + boff + kw) * 4;
                LDSM4(bh[p*2][0], bh[p*2][1], bh[p*2+1][0], bh[p*2+1][1], sB + off);
            }
            #pragma unroll
            for (int i = 0; i < 4; i++)
                #pragma unroll
                for (int j = 0; j < 4; j++)
                    MMA_F16(c[i][j], ah[i], bh[j]);
        }

        if (it + 2 < nIter) {
            __syncthreads();                       // all warps done reading stage it&1
            issueCp((it + 2) * GBK, it & 1);       // refill freed stage
        }
    }

    // ---- epilogue ----
    int cr = lane >> 2, cc = (lane & 3) * 2;
    #pragma unroll
    for (int i = 0; i < 4; i++) {
        #pragma unroll
        for (int j = 0; j < 4; j++) {
            int gn = n0 + wn + j * 8 + cc;
            #pragma unroll
            for (int half = 0; half < 2; half++) {
                int gm = m0 + wm + i * 16 + cr + half * 8;
                if (gm >= M) continue;
                float v0 = c[i][j][half * 2 + 0] * alpha;
                float v1 = c[i][j][half * 2 + 1] * alpha;
                if (bias) {
                    if (gn < N)     v0 += bias[gn];
                    if (gn + 1 < N) v1 += bias[gn + 1];
                }
                if (relu) { v0 = fmaxf(v0, 0.f); v1 = fmaxf(v1, 0.f); }
                if (Chalf) {
                    if (gn + 1 < N)
                        *(unsigned*)(Chalf + (long)gm * ldc + gn) = h2pack(v0, v1);
                } else {
                    if (gn + 1 < N)
                        *(float2*)(C + (long)gm * ldc + gn) = make_float2(v0, v1);
                    else if (gn < N)
                        C[(long)gm * ldc + gn] = v0;
                }
            }
        }
    }
}

// ---------------- weight f32 -> fp16 convert ----------------
__global__ void convert_h(const float* __restrict__ src,
                          unsigned* __restrict__ hiw, long n4)
{
    long i = (long)blockIdx.x * 256 + threadIdx.x;
    if (i >= n4) return;
    float4 v = ((const float4*)src)[i];
    ((uint2*)hiw)[i] = make_uint2(h2pack(v.x, v.y), h2pack(v.z, v.w));
}

// ---------------- embedding + positional encoding ----------------
__global__ void embed_kernel(const int* __restrict__ src, const float* __restrict__ emb,
                             float* __restrict__ x, h16* __restrict__ xh)
{
    long i = (long)blockIdx.x * 256 + threadIdx.x;
    int s = (int)(i >> 10);
    int d = (int)(i & 1023);
    int l = s & (LL - 1);
    int tok = src[s];
    int half2i = (d >> 1) * 2;
    float div = __expf(-(float)half2i * (logf(10000.f) / (float)DD));
    float arg = (float)l * div;
    float pe = (d & 1) ? cosf(arg) : sinf(arg);
    float v = emb[(long)tok * DD + d] * 32.0f + pe;
    x[i] = v;
    xh[i] = __float2half_rn(v);
}

// ---------------- head split / merge ----------------
__global__ void split_heads(const float* __restrict__ qkv,
                            h16* __restrict__ qh, h16* __restrict__ kh,
                            h16* __restrict__ vth)
{
    long i = (long)blockIdx.x * 256 + threadIdx.x;
    int s = (int)(i >> 10);
    int dc = (int)(i & 1023);
    int h = dc >> 6;
    int d = dc & 63;
    int b = s >> 9;
    int l = s & 511;
    long srcoff = (long)s * D3 + h * HD + d;
    long dst = (((long)(b * HH + h) * LL) + l) * HD + d;
    qh[dst] = __float2half_rn(qkv[srcoff]);
    kh[dst] = __float2half_rn(qkv[srcoff + DD]);
    long vdst = (((long)(b * HH + h) * HD) + d) * LL + l;
    vth[vdst] = __float2half_rn(qkv[srcoff + 2 * DD]);
}

__global__ void merge_heads(const float* __restrict__ av, h16* __restrict__ oh)
{
    long i = (long)blockIdx.x * 256 + threadIdx.x;
    int s = (int)(i >> 10);
    int dc = (int)(i & 1023);
    int h = dc >> 6;
    int d = dc & 63;
    int b = s >> 9;
    int l = s & 511;
    long srcoff = (((long)(b * HH + h) * LL) + l) * HD + d;
    oh[i] = __float2half_rn(av[srcoff]);
}

// ---------------- causal softmax: f32 scores -> fp16 probs ----------------
__global__ void softmax_causal(const float* __restrict__ sc, h16* __restrict__ ph)
{
    int row = blockIdx.x;
    int q = row & (LL - 1);
    const float* s = sc + (long)row * LL;
    h16* o = ph + (long)row * LL;
    int t = threadIdx.x;

    float mx = -1e30f;
    for (int k = t; k <= q; k += 128) mx = fmaxf(mx, s[k]);
    mx = blockReduceMax(mx);

    float sum = 0.f;
    for (int k = t; k <= q; k += 128) sum += expf(s[k] - mx);
    sum = blockReduceSum(sum);
    float inv = 1.f / sum;
    for (int k = t; k <= q; k += 128)
        o[k] = __float2half_rn(expf(s[k] - mx) * inv);
    h16 z = __float2half(0.f);
    for (int k = q + 1 + t; k < LL; k += 128) o[k] = z;
}

// ---------------- residual + layernorm ----------------
__global__ void add_ln(const float* __restrict__ a, const float* __restrict__ b,
                       const float* __restrict__ w, const float* __restrict__ bb,
                       float* __restrict__ out, h16* __restrict__ oh)
{
    int row = blockIdx.x;
    int t = threadIdx.x;
    const float* pa = a + (long)row * DD;
    const float* pb = b + (long)row * DD;
    float v[4];
    float s = 0.f;
    #pragma unroll
    for (int i = 0; i < 4; i++) {
        int d = t + i * 256;
        v[i] = pa[d] + pb[d];
        s += v[i];
    }
    s = blockReduceSum(s);
    float mean = s * (1.f / DD);
    float qq = 0.f;
    #pragma unroll
    for (int i = 0; i < 4; i++) {
        float dd = v[i] - mean;
        qq += dd * dd;
    }
    qq = blockReduceSum(qq);
    float inv = rsqrtf(qq * (1.f / DD) + 1e-5f);
    #pragma unroll
    for (int i = 0; i < 4; i++) {
        int d = t + i * 256;
        float o = (v[i] - mean) * inv * w[d] + bb[d];
        long idx = (long)row * DD + d;
        out[idx] = o;
        oh[idx] = __float2half_rn(o);
    }
}

// ---------------- MoE gating ----------------
__global__ void gate_topk(const float* __restrict__ x, const float* __restrict__ gw,
                          const float* __restrict__ gb,
                          int* __restrict__ topi, float* __restrict__ topw)
{
    __shared__ float sh[EE * 256];
    int s = blockIdx.x, t = threadIdx.x;
    float p[EE];
    #pragma unroll
    for (int e = 0; e < EE; e++) p[e] = 0.f;
    for (int d = t; d < DD; d += 256) {
        float xv = x[(long)s * DD + d];
        #pragma unroll
        for (int e = 0; e < EE; e++) p[e] += xv * gw[e * DD + d];
    }
    #pragma unroll
    for (int e = 0; e < EE; e++) sh[e * 256 + t] = p[e];
    __syncthreads();
    for (int o = 128; o > 0; o >>= 1) {
        if (t < o) {
            #pragma unroll
            for (int e = 0; e < EE; e++) sh[e * 256 + t] += sh[e * 256 + t + o];
        }
        __syncthreads();
    }
    if (t == 0) {
        float lg[EE];
        float mx = -1e30f;
        #pragma unroll
        for (int e = 0; e < EE; e++) { lg[e] = sh[e * 256] + gb[e]; mx = fmaxf(mx, lg[e]); }
        float sum = 0.f;
        #pragma unroll
        for (int e = 0; e < EE; e++) { lg[e] = expf(lg[e] - mx); sum += lg[e]; }
        float invs = 1.f / sum;
        #pragma unroll
        for (int e = 0; e < EE; e++) lg[e] *= invs;
        int i0 = 0;
        #pragma unroll
        for (int e = 1; e < EE; e++) if (lg[e] > lg[i0]) i0 = e;
        int i1 = (i0 == 0) ? 1 : 0;
        #pragma unroll
        for (int e = 0; e < EE; e++) if (e != i0 && lg[e] > lg[i1]) i1 = e;
        float w0 = lg[i0], w1 = lg[i1];
        float ws = 1.f / (w0 + w1);
        topi[2 * s]     = i0;
        topi[2 * s + 1] = i1;
        topw[2 * s]     = w0 * ws;
        topw[2 * s + 1] = w1 * ws;
    }
}

// ---------------- capacity routing ----------------
__global__ void route_kernel(const int* __restrict__ topi, const float* __restrict__ topw,
                             int* __restrict__ slot, float* __restrict__ slotw)
{
    __shared__ int cnt[256];
    int e = blockIdx.x;
    int t = threadIdx.x;
    int base = t * 8;
    int loc[8]; float lw[8]; int c = 0;
    #pragma unroll
    for (int i = 0; i < 8; i++) {
        int s = base + i;
        float w = -1.f;
        if (topi[2 * s] == e) w = topw[2 * s];
        else if (topi[2 * s + 1] == e) w = topw[2 * s + 1];
        if (w >= 0.f) { loc[c] = s; lw[c] = w; c++; }
    }
    cnt[t] = c;
    __syncthreads();
    for (int off = 1; off < 256; off <<= 1) {
        int v = 0;
        if (t >= off) v = cnt[t - off];
        __syncthreads();
        cnt[t] += v;
        __syncthreads();
    }
    int start = cnt[t] - c;
    for (int i = 0; i < c; i++) {
        int pos = start + i;
        if (pos < CAP) {
            slot[e * CAP + pos]  = loc[i];
            slotw[e * CAP + pos] = lw[i];
        }
    }
    int total = cnt[255];
    __syncthreads();
    for (int p = total + t; p < CAP; p += 256) {
        slot[e * CAP + p]  = -1;
        slotw[e * CAP + p] = 0.f;
    }
}

__global__ void gather_xe(const h16* __restrict__ xh, const int* __restrict__ slot,
                          h16* __restrict__ xeh)
{
    int sl = blockIdx.x;
    int t = slot[sl];
    unsigned* dh = (unsigned*)(xeh + (long)sl * DD);
    if (t < 0) {
        for (int d = threadIdx.x; d < DD / 2; d += 256) dh[d] = 0u;
    } else {
        const unsigned* sh = (const unsigned*)(xh + (long)t * DD);
        for (int d = threadIdx.x; d < DD / 2; d += 256) dh[d] = sh[d];
    }
}

__global__ void scatter_oe(const float* __restrict__ oe, const int* __restrict__ slot,
                           const float* __restrict__ slotw, float* __restrict__ y)
{
    int sl = blockIdx.x;
    int t = slot[sl];
    if (t < 0) return;
    float w = slotw[sl];
    const float* srcp = oe + (long)sl * DD;
    float* dst = y + (long)t * DD;
    for (int d = threadIdx.x; d < DD; d += 256) atomicAdd(&dst[d], srcp[d] * w);
}

// ---------------- host launcher ----------------
extern "C" void kernel_launch(void* const* d_in, const int* in_sizes, int n_in,
                              void* d_out, int out_size)
{
    const int*   src        = (const int*)  d_in[0];
    const float* emb        = (const float*)d_in[1];
    const float* in_proj_w  = (const float*)d_in[2];
    const float* in_proj_b  = (const float*)d_in[3];
    const float* out_proj_w = (const float*)d_in[4];
    const float* out_proj_b = (const float*)d_in[5];
    const float* ln1_w      = (const float*)d_in[6];
    const float* ln1_b      = (const float*)d_in[7];
    const float* ln2_w      = (const float*)d_in[8];
    const float* ln2_b      = (const float*)d_in[9];
    const float* gate_w     = (const float*)d_in[10];
    const float* gate_b     = (const float*)d_in[11];
    const float* w1         = (const float*)d_in[12];
    const float* b1         = (const float*)d_in[13];
    const float* w2         = (const float*)d_in[14];
    const float* b2         = (const float*)d_in[15];
    const float* dec_w      = (const float*)d_in[16];
    const float* dec_b      = (const float*)d_in[17];
    float* out = (float*)d_out;

    static int smem_set = 0;
    if (!smem_set) {
        cudaFuncSetAttribute(gemm_h16, cudaFuncAttributeMaxDynamicSharedMemorySize, GEMM_SMEM_BYTES);
        smem_set = 1;
    }

    float *x, *qkv, *sc, *av, *tmp, *oe, *topw, *slotw;
    int *topi, *slot;
    h16 *xh, *qh, *kh, *vth, *ph, *attnh, *xeh, *hh;
    h16 *wih, *woh, *w1h, *w2h, *dwh;

    cudaGetSymbolAddress((void**)&x,    g_x);
    cudaGetSymbolAddress((void**)&qkv,  g_qkv);
    cudaGetSymbolAddress((void**)&sc,   g_sc);
    cudaGetSymbolAddress((void**)&av,   g_av);
    cudaGetSymbolAddress((void**)&tmp,  g_tmp);
    cudaGetSymbolAddress((void**)&oe,   g_oe);
    cudaGetSymbolAddress((void**)&topi, g_topi);
    cudaGetSymbolAddress((void**)&topw, g_topw);
    cudaGetSymbolAddress((void**)&slot, g_slot);
    cudaGetSymbolAddress((void**)&slotw, g_slotw);
    cudaGetSymbolAddress((void**)&xh,   g_xh);
    cudaGetSymbolAddress((void**)&qh,   g_qh);
    cudaGetSymbolAddress((void**)&kh,   g_kh);
    cudaGetSymbolAddress((void**)&vth,  g_vth);
    cudaGetSymbolAddress((void**)&ph,   g_ph);
    cudaGetSymbolAddress((void**)&attnh, g_attnh);
    cudaGetSymbolAddress((void**)&xeh,  g_xeh);
    cudaGetSymbolAddress((void**)&hh,   g_hh);
    cudaGetSymbolAddress((void**)&wih,  g_wih);
    cudaGetSymbolAddress((void**)&woh,  g_woh);
    cudaGetSymbolAddress((void**)&w1h,  g_w1h);
    cudaGetSymbolAddress((void**)&w2h,  g_w2h);
    cudaGetSymbolAddress((void**)&dwh,  g_dwh);

    // ---- weight conversions (once per launch) ----
    auto conv = [&](const float* s, h16* h, long n) {
        long n4 = n / 4;
        convert_h<<<(unsigned)((n4 + 255) / 256), 256>>>(s, (unsigned*)h, n4);
    };
    conv(in_proj_w,  wih, (long)NLAYER * D3 * DD);
    conv(out_proj_w, woh, (long)NLAYER * DD * DD);
    conv(w1,         w1h, (long)NLAYER * EE * FF * DD);
    conv(w2,         w2h, (long)NLAYER * EE * DD * FF);
    conv(dec_w,      dwh, (long)VV * DD);

    embed_kernel<<<(SS * DD) / 256, 256>>>(src, emb, x, xh);

    for (int l = 0; l < NLAYER; l++) {
        const float* bi  = in_proj_b  + (long)l * D3;
        const float* bo  = out_proj_b + (long)l * DD;
        const float* gw  = gate_w     + (long)l * EE * DD;
        const float* gb  = gate_b     + (long)l * EE;
        const float* b1l = b1         + (long)l * EE * FF;
        const float* b2l = b2         + (long)l * EE * DD;
        const h16* wihl = wih + (long)l * D3 * DD;
        const h16* wohl = woh + (long)l * DD * DD;
        const h16* w1hl = w1h + (long)l * EE * FF * DD;
        const h16* w2hl = w2h + (long)l * EE * DD * FF;

        // qkv = x @ wi^T + bi   [2048 x 3072], K=1024
        gemm_h16<<<dim3(SS/GBM, D3/GBN, 1), 256, GEMM_SMEM_BYTES>>>(
            xh, wihl, bi, qkv, nullptr,
            SS, D3, DD, DD, DD, D3, 0, 0, 0, 0, 1.f, 0, 0, 0);

        split_heads<<<(SS * DD) / 256, 256>>>(qkv, qh, kh, vth);

        // scores = q @ k^T / 8   batch=64, K=64 (single iter), causal block skip
        gemm_h16<<<dim3(LL/GBM, LL/GBN, BB*HH), 256, GEMM_SMEM_BYTES>>>(
            qh, kh, nullptr, sc, nullptr,
            LL, LL, HD, HD, HD, LL,
            (long)LL*HD, (long)LL*HD, (long)LL*LL, 0, 0.125f, 0, 1, 0);

        softmax_causal<<<BB * HH * LL, 128>>>(sc, ph);

        // av = probs @ vt^T   batch=64, K capped by causal zeros (multiples of 128)
        gemm_h16<<<dim3(LL/GBM, 1, BB*HH), 256, GEMM_SMEM_BYTES>>>(
            ph, vth, nullptr, av, nullptr,
            LL, HD, LL, LL, LL, HD,
            (long)LL*LL, (long)HD*LL, (long)LL*HD, 0, 1.f, 0, 0, 1);

        merge_heads<<<(SS * DD) / 256, 256>>>(av, attnh);

        // proj = attn @ wo^T + bo
        gemm_h16<<<dim3(SS/GBM, DD/GBN, 1), 256, GEMM_SMEM_BYTES>>>(
            attnh, wohl, bo, tmp, nullptr,
            SS, DD, DD, DD, DD, DD, 0, 0, 0, 0, 1.f, 0, 0, 0);

        add_ln<<<SS, 256>>>(x, tmp, ln1_w + l * DD, ln1_b + l * DD, x, xh);

        // ---- MoE ----
        gate_topk<<<SS, 256>>>(x, gw, gb, topi, topw);
        route_kernel<<<EE, 256>>>(topi, topw, slot, slotw);
        gather_xe<<<EE * CAP, 256>>>(xh, slot, xeh);

        // h = relu(xe @ w1^T + b1) -> fp16 out   [320 x 4096] x8
        gemm_h16<<<dim3((CAP+GBM-1)/GBM, FF/GBN, EE), 256, GEMM_SMEM_BYTES>>>(
            xeh, w1hl, b1l, nullptr, hh,
            CAP, FF, DD, DD, DD, FF,
            (long)CAP*DD, (long)FF*DD, (long)CAP*FF, FF, 1.f, 1, 0, 0);

        // oe = h @ w2^T + b2   [320 x 1024] x8, K=4096
        gemm_h16<<<dim3((CAP+GBM-1)/GBM, DD/GBN, EE), 256, GEMM_SMEM_BYTES>>>(
            hh, w2hl, b2l, oe, nullptr,
            CAP, DD, FF, FF, FF, DD,
            (long)CAP*FF, (long)DD*FF, (long)CAP*DD, DD, 1.f, 0, 0, 0);

        cudaMemsetAsync(tmp, 0, (size_t)SS * DD * sizeof(float), 0);
        scatter_oe<<<EE * CAP, 256>>>(oe, slot, slotw, tmp);

        add_ln<<<SS, 256>>>(x, tmp, ln2_w + l * DD, ln2_b + l * DD, x, xh);
    }

    // logits = x @ dec_w^T + dec_b   [2048 x 32000], K=1024
    gemm_h16<<<dim3(SS/GBM, VV/GBN, 1), 256, GEMM_SMEM_BYTES>>>(
        xh, dwh, dec_b, out, nullptr,
        SS, VV, DD, DD, DD, VV, 0, 0, 0, 0, 1.f, 0, 0, 0);
}

// round 16
// speedup vs baseline: 1.1624x; 1.1624x over previous
#include <cuda_runtime.h>
#include <cuda_fp16.h>
#include <math.h>

// ---------------- problem constants ----------------
#define BB 4
#define LL 512
#define VV 32000
#define DD 1024
#define HH 16
#define HD 64
#define NLAYER 2
#define EE 8
#define KK 2
#define FF 4096
#define SS (BB*LL)      // 2048
#define CAP 320
#define D3 (3*DD)       // 3072

typedef __half h16;

// ---------------- static scratch (f32) ----------------
__device__ float g_x[SS*DD];
__device__ float g_qkv[SS*D3];
__device__ float g_sc[BB*HH*LL*LL];     // 64 MB scores (f32 — precision critical)
__device__ float g_av[SS*DD];
__device__ float g_tmp[SS*DD];
__device__ float g_oe[EE*CAP*DD];
__device__ int   g_topi[SS*2];
__device__ float g_topw[SS*2];
__device__ int   g_slot[EE*CAP];
__device__ float g_slotw[EE*CAP];

// ---------------- fp16 activation buffers ----------------
__device__ h16 g_ph[BB*HH*LL*LL];       // probs fp16 (32MB)
__device__ h16 g_xh[SS*DD];
__device__ h16 g_qh[SS*DD];
__device__ h16 g_kh[SS*DD];
__device__ h16 g_vth[SS*DD];            // V^T per head [bh, d, l]
__device__ h16 g_attnh[SS*DD];
__device__ h16 g_xeh[EE*CAP*DD];
__device__ h16 g_hh[EE*CAP*FF];

// ---------------- fp16 weights (converted once/launch) ----------------
__device__ h16 g_wih[NLAYER*D3*DD];
__device__ h16 g_woh[NLAYER*DD*DD];
__device__ h16 g_w1h[NLAYER*EE*FF*DD];
__device__ h16 g_w2h[NLAYER*EE*DD*FF];
__device__ h16 g_dwh[VV*DD];

// ---------------- reductions ----------------
__device__ __forceinline__ float blockReduceSum(float v){
    __shared__ float sh[32];
    int lane = threadIdx.x & 31, wid = threadIdx.x >> 5;
    int nw = (blockDim.x + 31) >> 5;
    #pragma unroll
    for (int o = 16; o > 0; o >>= 1) v += __shfl_down_sync(0xffffffffu, v, o);
    __syncthreads();
    if (lane == 0) sh[wid] = v;
    __syncthreads();
    if (wid == 0) {
        v = (lane < nw) ? sh[lane] : 0.f;
        #pragma unroll
        for (int o = 16; o > 0; o >>= 1) v += __shfl_down_sync(0xffffffffu, v, o);
        if (lane == 0) sh[0] = v;
    }
    __syncthreads();
    return sh[0];
}

__device__ __forceinline__ float blockReduceMax(float v){
    __shared__ float sh[32];
    int lane = threadIdx.x & 31, wid = threadIdx.x >> 5;
    int nw = (blockDim.x + 31) >> 5;
    #pragma unroll
    for (int o = 16; o > 0; o >>= 1) v = fmaxf(v, __shfl_down_sync(0xffffffffu, v, o));
    __syncthreads();
    if (lane == 0) sh[wid] = v;
    __syncthreads();
    if (wid == 0) {
        v = (lane < nw) ? sh[lane] : -1e30f;
        #pragma unroll
        for (int o = 16; o > 0; o >>= 1) v = fmaxf(v, __shfl_down_sync(0xffffffffu, v, o));
        if (lane == 0) sh[0] = v;
    }
    __syncthreads();
    return sh[0];
}

// ---------------- helpers ----------------
#define MMA_F16(d, a, b) \
    asm volatile("mma.sync.aligned.m16n8k16.row.col.f32.f16.f16.f32 " \
        "{%0,%1,%2,%3},{%4,%5,%6,%7},{%8,%9},{%0,%1,%2,%3};" \
        : "+f"(d[0]), "+f"(d[1]), "+f"(d[2]), "+f"(d[3]) \
        : "r"(a[0]), "r"(a[1]), "r"(a[2]), "r"(a[3]), "r"(b[0]), "r"(b[1]))

#define LDSM4(r0, r1, r2, r3, addr) \
    asm volatile("ldmatrix.sync.aligned.m8n8.x4.shared.b16 {%0,%1,%2,%3}, [%4];" \
        : "=r"(r0), "=r"(r1), "=r"(r2), "=r"(r3) : "r"(addr))

__device__ __forceinline__ unsigned h2pack(float x, float y){
    __half2 H; H.x = __float2half_rn(x); H.y = __float2half_rn(y);
    return *(unsigned*)&H;
}
__device__ __forceinline__ void cp16(unsigned dst, const void* src, bool pred){
    asm volatile("cp.async.cg.shared.global [%0], [%1], 16, %2;"
        :: "r"(dst), "l"(src), "r"(pred ? 16 : 0));
}

// ============================================================
// Pure-fp16 tensor-core GEMM (single pass) — R13 structure:
//   C = act(alpha * A(MxK) * B(NxK)^T + bias)
// Block 128x128x32, 8 warps, warp tile 64x32, m16n8k16,
// 3-stage cp.async, 1 barrier/iter.
// ============================================================
#define GBM 128
#define GBN 128
#define GBK 32
#define LDW 20                            // row stride in 32-bit words
#define TILE_B (GBM * LDW * 4)            // 10240 B per tile
#define STAGE_B (2u * TILE_B)             // A, B = 20480 B
#define NSTAGE 3
#define GEMM_SMEM_BYTES (NSTAGE * STAGE_B)  // 61440 B

__global__ void __launch_bounds__(256, 2)
gemm_h16(const h16* __restrict__ A, const h16* __restrict__ Bm,
         const float* __restrict__ bias, float* __restrict__ C,
         h16* __restrict__ Chalf,
         int M, int N, int K, int lda, int ldb, int ldc,
         long aStride, long bStride, long cStride, long biasStride,
         float alpha, int relu, int causal, int kcap)
{
    extern __shared__ char smem[];
    int m0 = blockIdx.x * GBM;
    int n0 = blockIdx.y * GBN;
    if (causal && n0 > m0 + GBM - 1) return;             // fully-masked causal block
    if (kcap) { int ke = m0 + GBM; if (ke < K) K = ke; } // zero prob cols past diag

    int z = blockIdx.z;
    A  += (long)z * aStride;
    Bm += (long)z * bStride;
    if (C)     C     += (long)z * cStride;
    if (Chalf) Chalf += (long)z * cStride;
    if (bias)  bias  += (long)z * biasStride;

    int tid = threadIdx.x;
    int wid = tid >> 5, lane = tid & 31;
    int wm = (wid & 1) * 64;
    int wn = (wid >> 1) * 32;

    float c[4][4][4];
    #pragma unroll
    for (int i = 0; i < 4; i++)
        #pragma unroll
        for (int j = 0; j < 4; j++)
            #pragma unroll
            for (int r = 0; r < 4; r++) c[i][j][r] = 0.f;

    int cpRow = tid >> 1;
    int cpC   = (tid & 1) * 2;       // chunk index 0 or 2 (each = 16B = 8 fp16)
    int gmA = m0 + cpRow;  bool okA = gmA < M;  if (!okA) gmA = 0;
    int gnB = n0 + cpRow;  bool okB = gnB < N;  if (!okB) gnB = 0;

    unsigned sbase = (unsigned)__cvta_generic_to_shared(smem);
    unsigned rowOff = (unsigned)(cpRow * (LDW * 4) + cpC * 16);

    auto issueCp = [&](int kt, int s) {
        unsigned base = sbase + s * STAGE_B;
        const h16* pa = A  + (long)gmA * lda + kt + cpC * 8;
        const h16* pb = Bm + (long)gnB * ldb + kt + cpC * 8;
        cp16(base + rowOff,               pa,     okA);
        cp16(base + rowOff + 16,          pa + 8, okA);
        cp16(base + TILE_B + rowOff,      pb,     okB);
        cp16(base + TILE_B + rowOff + 16, pb + 8, okB);
        asm volatile("cp.async.commit_group;" ::: "memory");
    };

    int aoff = (lane & 15) * LDW + ((lane >> 4) << 2);
    int boff = ((lane & 7) + ((lane >> 4) & 1) * 8) * LDW + ((lane >> 3) & 1) * 4;

    int nIter = K / GBK;     // always >= 2 for this model
    issueCp(0, 0);
    issueCp(GBK, 1);

    for (int it = 0; it < nIter; it++) {
        if (it < nIter - 1) asm volatile("cp.async.wait_group 1;" ::: "memory");
        else                asm volatile("cp.async.wait_group 0;" ::: "memory");
        __syncthreads();   // stage it%3 ready; all threads done reading stage (it+2)%3

        int s = it % NSTAGE;
        unsigned sA = sbase + s * STAGE_B;
        unsigned sB = sA + TILE_B;

        #pragma unroll
        for (int ks = 0; ks < 2; ks++) {
            int kw = ks * 8;
            unsigned ah[4][4], bh[4][2];
            #pragma unroll
            for (int i = 0; i < 4; i++) {
                unsigned off = ((wm + i * 16) * LDW + aoff + kw) * 4;
                LDSM4(ah[i][0], ah[i][1], ah[i][2], ah[i][3], sA + off);
            }
            #pragma unroll
            for (int p = 0; p < 2; p++) {
                unsigned off = ((wn + p * 16) * LDW + boff + kw) * 4;
                LDSM4(bh[p*2][0], bh[p*2][1], bh[p*2+1][0], bh[p*2+1][1], sB + off);
            }
            #pragma unroll
            for (int i = 0; i < 4; i++)
                #pragma unroll
                for (int j = 0; j < 4; j++)
                    MMA_F16(c[i][j], ah[i], bh[j]);
        }

        if (it + 2 < nIter) issueCp((it + 2) * GBK, (it + 2) % NSTAGE);
    }

    // ---- epilogue ----
    int cr = lane >> 2, cc = (lane & 3) * 2;
    #pragma unroll
    for (int i = 0; i < 4; i++) {
        #pragma unroll
        for (int j = 0; j < 4; j++) {
            int gn = n0 + wn + j * 8 + cc;
            #pragma unroll
            for (int half = 0; half < 2; half++) {
                int gm = m0 + wm + i * 16 + cr + half * 8;
                if (gm >= M) continue;
                float v0 = c[i][j][half * 2 + 0] * alpha;
                float v1 = c[i][j][half * 2 + 1] * alpha;
                if (bias) {
                    if (gn < N)     v0 += bias[gn];
                    if (gn + 1 < N) v1 += bias[gn + 1];
                }
                if (relu) { v0 = fmaxf(v0, 0.f); v1 = fmaxf(v1, 0.f); }
                if (Chalf) {
                    if (gn + 1 < N)
                        *(unsigned*)(Chalf + (long)gm * ldc + gn) = h2pack(v0, v1);
                } else {
                    if (gn + 1 < N)
                        *(float2*)(C + (long)gm * ldc + gn) = make_float2(v0, v1);
                    else if (gn < N)
                        C[(long)gm * ldc + gn] = v0;
                }
            }
        }
    }
}

// ---------------- weight f32 -> fp16 convert ----------------
__global__ void convert_h(const float* __restrict__ src,
                          unsigned* __restrict__ hiw, long n4)
{
    long i = (long)blockIdx.x * 256 + threadIdx.x;
    if (i >= n4) return;
    float4 v = ((const float4*)src)[i];
    ((uint2*)hiw)[i] = make_uint2(h2pack(v.x, v.y), h2pack(v.z, v.w));
}

// ---------------- embedding + positional encoding ----------------
__global__ void embed_kernel(const int* __restrict__ src, const float* __restrict__ emb,
                             float* __restrict__ x, h16* __restrict__ xh)
{
    long i = (long)blockIdx.x * 256 + threadIdx.x;
    int s = (int)(i >> 10);
    int d = (int)(i & 1023);
    int l = s & (LL - 1);
    int tok = src[s];
    int half2i = (d >> 1) * 2;
    float div = __expf(-(float)half2i * (logf(10000.f) / (float)DD));
    float arg = (float)l * div;
    float pe = (d & 1) ? cosf(arg) : sinf(arg);
    float v = emb[(long)tok * DD + d] * 32.0f + pe;
    x[i] = v;
    xh[i] = __float2half_rn(v);
}

// ---------------- head split / merge ----------------
__global__ void split_heads(const float* __restrict__ qkv,
                            h16* __restrict__ qh, h16* __restrict__ kh,
                            h16* __restrict__ vth)
{
    long i = (long)blockIdx.x * 256 + threadIdx.x;
    int s = (int)(i >> 10);
    int dc = (int)(i & 1023);
    int h = dc >> 6;
    int d = dc & 63;
    int b = s >> 9;
    int l = s & 511;
    long srcoff = (long)s * D3 + h * HD + d;
    long dst = (((long)(b * HH + h) * LL) + l) * HD + d;
    qh[dst] = __float2half_rn(qkv[srcoff]);
    kh[dst] = __float2half_rn(qkv[srcoff + DD]);
    long vdst = (((long)(b * HH + h) * HD) + d) * LL + l;
    vth[vdst] = __float2half_rn(qkv[srcoff + 2 * DD]);
}

__global__ void merge_heads(const float* __restrict__ av, h16* __restrict__ oh)
{
    long i = (long)blockIdx.x * 256 + threadIdx.x;
    int s = (int)(i >> 10);
    int dc = (int)(i & 1023);
    int h = dc >> 6;
    int d = dc & 63;
    int b = s >> 9;
    int l = s & 511;
    long srcoff = (((long)(b * HH + h) * LL) + l) * HD + d;
    oh[i] = __float2half_rn(av[srcoff]);
}

// ---------------- causal softmax: f32 scores -> fp16 probs ----------------
__global__ void softmax_causal(const float* __restrict__ sc, h16* __restrict__ ph)
{
    int row = blockIdx.x;
    int q = row & (LL - 1);
    const float* s = sc + (long)row * LL;
    h16* o = ph + (long)row * LL;
    int t = threadIdx.x;

    float mx = -1e30f;
    for (int k = t; k <= q; k += 128) mx = fmaxf(mx, s[k]);
    mx = blockReduceMax(mx);

    float sum = 0.f;
    for (int k = t; k <= q; k += 128) sum += expf(s[k] - mx);
    sum = blockReduceSum(sum);
    float inv = 1.f / sum;
    for (int k = t; k <= q; k += 128)
        o[k] = __float2half_rn(expf(s[k] - mx) * inv);
    h16 z = __float2half(0.f);
    for (int k = q + 1 + t; k < LL; k += 128) o[k] = z;
}

// ---------------- residual + layernorm ----------------
__global__ void add_ln(const float* __restrict__ a, const float* __restrict__ b,
                       const float* __restrict__ w, const float* __restrict__ bb,
                       float* __restrict__ out, h16* __restrict__ oh)
{
    int row = blockIdx.x;
    int t = threadIdx.x;
    const float* pa = a + (long)row * DD;
    const float* pb = b + (long)row * DD;
    float v[4];
    float s = 0.f;
    #pragma unroll
    for (int i = 0; i < 4; i++) {
        int d = t + i * 256;
        v[i] = pa[d] + pb[d];
        s += v[i];
    }
    s = blockReduceSum(s);
    float mean = s * (1.f / DD);
    float qq = 0.f;
    #pragma unroll
    for (int i = 0; i < 4; i++) {
        float dd = v[i] - mean;
        qq += dd * dd;
    }
    qq = blockReduceSum(qq);
    float inv = rsqrtf(qq * (1.f / DD) + 1e-5f);
    #pragma unroll
    for (int i = 0; i < 4; i++) {
        int d = t + i * 256;
        float o = (v[i] - mean) * inv * w[d] + bb[d];
        long idx = (long)row * DD + d;
        out[idx] = o;
        oh[idx] = __float2half_rn(o);
    }
}

// ---------------- MoE gating ----------------
__global__ void gate_topk(const float* __restrict__ x, const float* __restrict__ gw,
                          const float* __restrict__ gb,
                          int* __restrict__ topi, float* __restrict__ topw)
{
    __shared__ float sh[EE * 256];
    int s = blockIdx.x, t = threadIdx.x;
    float p[EE];
    #pragma unroll
    for (int e = 0; e < EE; e++) p[e] = 0.f;
    for (int d = t; d < DD; d += 256) {
        float xv = x[(long)s * DD + d];
        #pragma unroll
        for (int e = 0; e < EE; e++) p[e] += xv * gw[e * DD + d];
    }
    #pragma unroll
    for (int e = 0; e < EE; e++) sh[e * 256 + t] = p[e];
    __syncthreads();
    for (int o = 128; o > 0; o >>= 1) {
        if (t < o) {
            #pragma unroll
            for (int e = 0; e < EE; e++) sh[e * 256 + t] += sh[e * 256 + t + o];
        }
        __syncthreads();
    }
    if (t == 0) {
        float lg[EE];
        float mx = -1e30f;
        #pragma unroll
        for (int e = 0; e < EE; e++) { lg[e] = sh[e * 256] + gb[e]; mx = fmaxf(mx, lg[e]); }
        float sum = 0.f;
        #pragma unroll
        for (int e = 0; e < EE; e++) { lg[e] = expf(lg[e] - mx); sum += lg[e]; }
        float invs = 1.f / sum;
        #pragma unroll
        for (int e = 0; e < EE; e++) lg[e] *= invs;
        int i0 = 0;
        #pragma unroll
        for (int e = 1; e < EE; e++) if (lg[e] > lg[i0]) i0 = e;
        int i1 = (i0 == 0) ? 1 : 0;
        #pragma unroll
        for (int e = 0; e < EE; e++) if (e != i0 && lg[e] > lg[i1]) i1 = e;
        float w0 = lg[i0], w1 = lg[i1];
        float ws = 1.f / (w0 + w1);
        topi[2 * s]     = i0;
        topi[2 * s + 1] = i1;
        topw[2 * s]     = w0 * ws;
        topw[2 * s + 1] = w1 * ws;
    }
}

// ---------------- capacity routing ----------------
__global__ void route_kernel(const int* __restrict__ topi, const float* __restrict__ topw,
                             int* __restrict__ slot, float* __restrict__ slotw)
{
    __shared__ int cnt[256];
    int e = blockIdx.x;
    int t = threadIdx.x;
    int base = t * 8;
    int loc[8]; float lw[8]; int c = 0;
    #pragma unroll
    for (int i = 0; i < 8; i++) {
        int s = base + i;
        float w = -1.f;
        if (topi[2 * s] == e) w = topw[2 * s];
        else if (topi[2 * s + 1] == e) w = topw[2 * s + 1];
        if (w >= 0.f) { loc[c] = s; lw[c] = w; c++; }
    }
    cnt[t] = c;
    __syncthreads();
    for (int off = 1; off < 256; off <<= 1) {
        int v = 0;
        if (t >= off) v = cnt[t - off];
        __syncthreads();
        cnt[t] += v;
        __syncthreads();
    }
    int start = cnt[t] - c;
    for (int i = 0; i < c; i++) {
        int pos = start + i;
        if (pos < CAP) {
            slot[e * CAP + pos]  = loc[i];
            slotw[e * CAP + pos] = lw[i];
        }
    }
    int total = cnt[255];
    __syncthreads();
    for (int p = total + t; p < CAP; p += 256) {
        slot[e * CAP + p]  = -1;
        slotw[e * CAP + p] = 0.f;
    }
}

__global__ void gather_xe(const h16* __restrict__ xh, const int* __restrict__ slot,
                          h16* __restrict__ xeh)
{
    int sl = blockIdx.x;
    int t = slot[sl];
    unsigned* dh = (unsigned*)(xeh + (long)sl * DD);
    if (t < 0) {
        for (int d = threadIdx.x; d < DD / 2; d += 256) dh[d] = 0u;
    } else {
        const unsigned* sh = (const unsigned*)(xh + (long)t * DD);
        for (int d = threadIdx.x; d < DD / 2; d += 256) dh[d] = sh[d];
    }
}

__global__ void scatter_oe(const float* __restrict__ oe, const int* __restrict__ slot,
                           const float* __restrict__ slotw, float* __restrict__ y)
{
    int sl = blockIdx.x;
    int t = slot[sl];
    if (t < 0) return;
    float w = slotw[sl];
    const float* srcp = oe + (long)sl * DD;
    float* dst = y + (long)t * DD;
    for (int d = threadIdx.x; d < DD; d += 256) atomicAdd(&dst[d], srcp[d] * w);
}

// ---------------- host launcher ----------------
extern "C" void kernel_launch(void* const* d_in, const int* in_sizes, int n_in,
                              void* d_out, int out_size)
{
    const int*   src        = (const int*)  d_in[0];
    const float* emb        = (const float*)d_in[1];
    const float* in_proj_w  = (const float*)d_in[2];
    const float* in_proj_b  = (const float*)d_in[3];
    const float* out_proj_w = (const float*)d_in[4];
    const float* out_proj_b = (const float*)d_in[5];
    const float* ln1_w      = (const float*)d_in[6];
    const float* ln1_b      = (const float*)d_in[7];
    const float* ln2_w      = (const float*)d_in[8];
    const float* ln2_b      = (const float*)d_in[9];
    const float* gate_w     = (const float*)d_in[10];
    const float* gate_b     = (const float*)d_in[11];
    const float* w1         = (const float*)d_in[12];
    const float* b1         = (const float*)d_in[13];
    const float* w2         = (const float*)d_in[14];
    const float* b2         = (const float*)d_in[15];
    const float* dec_w      = (const float*)d_in[16];
    const float* dec_b      = (const float*)d_in[17];
    float* out = (float*)d_out;

    static int inited = 0;
    static cudaStream_t s2;
    static cudaEvent_t evF, evJ1, evJ2;
    if (!inited) {
        cudaFuncSetAttribute(gemm_h16, cudaFuncAttributeMaxDynamicSharedMemorySize, GEMM_SMEM_BYTES);
        cudaStreamCreateWithFlags(&s2, cudaStreamNonBlocking);
        cudaEventCreateWithFlags(&evF,  cudaEventDisableTiming);
        cudaEventCreateWithFlags(&evJ1, cudaEventDisableTiming);
        cudaEventCreateWithFlags(&evJ2, cudaEventDisableTiming);
        inited = 1;
    }

    float *x, *qkv, *sc, *av, *tmp, *oe, *topw, *slotw;
    int *topi, *slot;
    h16 *ph, *xh, *qh, *kh, *vth, *attnh, *xeh, *hh;
    h16 *wih, *woh, *w1h, *w2h, *dwh;

    cudaGetSymbolAddress((void**)&x,    g_x);
    cudaGetSymbolAddress((void**)&qkv,  g_qkv);
    cudaGetSymbolAddress((void**)&sc,   g_sc);
    cudaGetSymbolAddress((void**)&av,   g_av);
    cudaGetSymbolAddress((void**)&tmp,  g_tmp);
    cudaGetSymbolAddress((void**)&oe,   g_oe);
    cudaGetSymbolAddress((void**)&topi, g_topi);
    cudaGetSymbolAddress((void**)&topw, g_topw);
    cudaGetSymbolAddress((void**)&slot, g_slot);
    cudaGetSymbolAddress((void**)&slotw, g_slotw);
    cudaGetSymbolAddress((void**)&ph,   g_ph);
    cudaGetSymbolAddress((void**)&xh,   g_xh);
    cudaGetSymbolAddress((void**)&qh,   g_qh);
    cudaGetSymbolAddress((void**)&kh,   g_kh);
    cudaGetSymbolAddress((void**)&vth,  g_vth);
    cudaGetSymbolAddress((void**)&attnh, g_attnh);
    cudaGetSymbolAddress((void**)&xeh,  g_xeh);
    cudaGetSymbolAddress((void**)&hh,   g_hh);
    cudaGetSymbolAddress((void**)&wih,  g_wih);
    cudaGetSymbolAddress((void**)&woh,  g_woh);
    cudaGetSymbolAddress((void**)&w1h,  g_w1h);
    cudaGetSymbolAddress((void**)&w2h,  g_w2h);
    cudaGetSymbolAddress((void**)&dwh,  g_dwh);

    auto conv = [&](const float* s, h16* h, long n, cudaStream_t st) {
        long n4 = n / 4;
        convert_h<<<(unsigned)((n4 + 255) / 256), 256, 0, st>>>(s, (unsigned*)h, n4);
    };

    // ---- critical-path converts (layer-0 attention weights) on stream 0 ----
    conv(in_proj_w,  wih, (long)D3 * DD, 0);
    conv(out_proj_w, woh, (long)DD * DD, 0);

    // ---- fork side stream: remaining converts overlap layer-0 compute ----
    cudaEventRecord(evF, 0);
    cudaStreamWaitEvent(s2, evF, 0);
    conv(w1, w1h, (long)EE * FF * DD, s2);              // layer-0 MoE weights
    conv(w2, w2h, (long)EE * DD * FF, s2);
    cudaEventRecord(evJ1, s2);                          // needed before layer-0 MoE
    conv(in_proj_w  + (long)D3 * DD, wih + (long)D3 * DD, (long)D3 * DD, s2);
    conv(out_proj_w + (long)DD * DD, woh + (long)DD * DD, (long)DD * DD, s2);
    conv(w1 + (long)EE * FF * DD, w1h + (long)EE * FF * DD, (long)EE * FF * DD, s2);
    conv(w2 + (long)EE * DD * FF, w2h + (long)EE * DD * FF, (long)EE * DD * FF, s2);
    conv(dec_w, dwh, (long)VV * DD, s2);
    cudaEventRecord(evJ2, s2);                          // needed before layer 1

    embed_kernel<<<(SS * DD) / 256, 256>>>(src, emb, x, xh);

    for (int l = 0; l < NLAYER; l++) {
        if (l == 1) cudaStreamWaitEvent(0, evJ2, 0);    // layer-1 + decoder weights ready

        const float* bi  = in_proj_b  + (long)l * D3;
        const float* bo  = out_proj_b + (long)l * DD;
        const float* gw  = gate_w     + (long)l * EE * DD;
        const float* gb  = gate_b     + (long)l * EE;
        const float* b1l = b1         + (long)l * EE * FF;
        const float* b2l = b2         + (long)l * EE * DD;
        const h16* wihl = wih + (long)l * D3 * DD;
        const h16* wohl = woh + (long)l * DD * DD;
        const h16* w1hl = w1h + (long)l * EE * FF * DD;
        const h16* w2hl = w2h + (long)l * EE * DD * FF;

        // qkv = x @ wi^T + bi   [2048 x 3072], K=1024
        gemm_h16<<<dim3(SS/GBM, D3/GBN, 1), 256, GEMM_SMEM_BYTES>>>(
            xh, wihl, bi, qkv, nullptr,
            SS, D3, DD, DD, DD, D3, 0, 0, 0, 0, 1.f, 0, 0, 0);

        split_heads<<<(SS * DD) / 256, 256>>>(qkv, qh, kh, vth);

        // scores = q @ k^T / 8 -> f32 (precision critical)   batch=64, causal skip
        gemm_h16<<<dim3(LL/GBM, LL/GBN, BB*HH), 256, GEMM_SMEM_BYTES>>>(
            qh, kh, nullptr, sc, nullptr,
            LL, LL, HD, HD, HD, LL,
            (long)LL*HD, (long)LL*HD, (long)LL*LL, 0, 0.125f, 0, 1, 0);

        softmax_causal<<<BB * HH * LL, 128>>>(sc, ph);

        // av = probs @ vt^T   batch=64, K capped by causal zeros
        gemm_h16<<<dim3(LL/GBM, 1, BB*HH), 256, GEMM_SMEM_BYTES>>>(
            ph, vth, nullptr, av, nullptr,
            LL, HD, LL, LL, LL, HD,
            (long)LL*LL, (long)HD*LL, (long)LL*HD, 0, 1.f, 0, 0, 1);

        merge_heads<<<(SS * DD) / 256, 256>>>(av, attnh);

        // proj = attn @ wo^T + bo
        gemm_h16<<<dim3(SS/GBM, DD/GBN, 1), 256, GEMM_SMEM_BYTES>>>(
            attnh, wohl, bo, tmp, nullptr,
            SS, DD, DD, DD, DD, DD, 0, 0, 0, 0, 1.f, 0, 0, 0);

        add_ln<<<SS, 256>>>(x, tmp, ln1_w + l * DD, ln1_b + l * DD, x, xh);

        // ---- MoE ----
        gate_topk<<<SS, 256>>>(x, gw, gb, topi, topw);
        route_kernel<<<EE, 256>>>(topi, topw, slot, slotw);
        gather_xe<<<EE * CAP, 256>>>(xh, slot, xeh);

        if (l == 0) cudaStreamWaitEvent(0, evJ1, 0);    // layer-0 MoE weights ready

        // h = relu(xe @ w1^T + b1) -> fp16 out   [320 x 4096] x8
        gemm_h16<<<dim3((CAP+GBM-1)/GBM, FF/GBN, EE), 256, GEMM_SMEM_BYTES>>>(
            xeh, w1hl, b1l, nullptr, hh,
            CAP, FF, DD, DD, DD, FF,
            (long)CAP*DD, (long)FF*DD, (long)CAP*FF, FF, 1.f, 1, 0, 0);

        // oe = h @ w2^T + b2   [320 x 1024] x8, K=4096
        gemm_h16<<<dim3((CAP+GBM-1)/GBM, DD/GBN, EE), 256, GEMM_SMEM_BYTES>>>(
            hh, w2hl, b2l, oe, nullptr,
            CAP, DD, FF, FF, FF, DD,
            (long)CAP*FF, (long)DD*FF, (long)CAP*DD, DD, 1.f, 0, 0, 0);

        cudaMemsetAsync(tmp, 0, (size_t)SS * DD * sizeof(float), 0);
        scatter_oe<<<EE * CAP, 256>>>(oe, slot, slotw, tmp);

        add_ln<<<SS, 256>>>(x, tmp, ln2_w + l * DD, ln2_b + l * DD, x, xh);
    }

    // logits = x @ dec_w^T + dec_b   [2048 x 32000], K=1024
    gemm_h16<<<dim3(SS/GBM, VV/GBN, 1), 256, GEMM_SMEM_BYTES>>>(
        xh, dwh, dec_b, out, nullptr,
        SS, VV, DD, DD, DD, VV, 0, 0, 0, 0, 1.f, 0, 0, 0);
}